// round 5
// baseline (speedup 1.0000x reference)
#include <cuda_runtime.h>

#define N_NODES 50000
#define N_EDGES 800000
#define DIM     256
#define KDIM    512            // concat(mean, root) K dimension
#define SCAN_B  1024
#define SCAN_NB 49             // ceil(50000/1024)

// ---------------- static device scratch (no allocations allowed) ----------------
__device__ float g_xcat[(size_t)N_NODES * KDIM];  // [N,512]: cols 0..255 = mean, 256..511 = root feat
__device__ float g_h[(size_t)N_NODES * DIM];      // layer-1 output (relu'd, normalized)
__device__ int   g_deg[N_NODES];
__device__ float g_inv[N_NODES];
__device__ int   g_rs[N_NODES];                   // CSR row start
__device__ int   g_cur[N_NODES];                  // scatter cursors
__device__ int   g_srt[N_EDGES];                  // src ids sorted by dst
__device__ int   g_bsum[64];
__device__ int   g_is64;                          // 1 if edge buffer is int64, 0 if int32
__device__ float g_w1[KDIM * DIM];                // Wcat layer1: [512][256], w[k][j] = W[j][k]
__device__ float g_w2[KDIM * DIM];

// ---------------- edge dtype detection ----------------
// View buffer as int32. For little-endian int64 values in [0, 50000), every odd
// 32-bit word is 0. For genuine int32 edge data, 32 consecutive odd words all
// being zero has probability ~(1/50000)^32 ~ 0.
__global__ void k_detect(const int* __restrict__ e32) {
    if (threadIdx.x == 0 && blockIdx.x == 0) {
        int is64 = 1;
        for (int i = 0; i < 32; i++)
            if (e32[2 * i + 1] != 0) is64 = 0;
        g_is64 = is64;
    }
}

__device__ __forceinline__ int edge_at(const void* edge, long long idx) {
    if (g_is64) return (int)((const long long*)edge)[idx];
    return ((const int*)edge)[idx];
}

// ---------------- CSR build ----------------
__global__ void k_zero_deg() {
    int i = blockIdx.x * blockDim.x + threadIdx.x;
    if (i < N_NODES) g_deg[i] = 0;
}

__global__ void k_hist(const void* __restrict__ edge) {
    int e = blockIdx.x * blockDim.x + threadIdx.x;
    if (e < N_EDGES) {
        int d = edge_at(edge, (long long)N_EDGES + e);
        if ((unsigned)d < (unsigned)N_NODES)          // crash-proof guard
            atomicAdd(&g_deg[d], 1);
    }
}

__global__ void k_scan1() {
    __shared__ int s[SCAN_B];
    int i = blockIdx.x * SCAN_B + threadIdx.x;
    int v = (i < N_NODES) ? g_deg[i] : 0;
    s[threadIdx.x] = v;
    __syncthreads();
    for (int off = 1; off < SCAN_B; off <<= 1) {
        int t = (threadIdx.x >= off) ? s[threadIdx.x - off] : 0;
        __syncthreads();
        s[threadIdx.x] += t;
        __syncthreads();
    }
    if (i < N_NODES) g_rs[i] = s[threadIdx.x] - v;   // exclusive within block
    if (threadIdx.x == SCAN_B - 1) g_bsum[blockIdx.x] = s[SCAN_B - 1];
}

__global__ void k_scan2(int nblk) {
    if (threadIdx.x == 0 && blockIdx.x == 0) {
        int acc = 0;
        for (int b = 0; b < nblk; b++) { int t = g_bsum[b]; g_bsum[b] = acc; acc += t; }
    }
}

__global__ void k_scan3() {
    int i = blockIdx.x * SCAN_B + threadIdx.x;
    if (i < N_NODES) {
        int rs = g_rs[i] + g_bsum[blockIdx.x];
        g_rs[i]  = rs;
        g_cur[i] = rs;
        int d = g_deg[i];
        g_inv[i] = 1.0f / (float)(d > 1 ? d : 1);
    }
}

__global__ void k_scatter(const void* __restrict__ edge) {
    int e = blockIdx.x * blockDim.x + threadIdx.x;
    if (e < N_EDGES) {
        int d = edge_at(edge, (long long)N_EDGES + e);
        if ((unsigned)d < (unsigned)N_NODES) {        // must match k_hist guard
            int s = edge_at(edge, e);
            if ((unsigned)s >= (unsigned)N_NODES) s = 0;  // crash-proof clamp
            int p = atomicAdd(&g_cur[d], 1);
            g_srt[p] = s;
        }
    }
}

// ---------------- weight concat+transpose: wcat[k][j] = (k<256 ? Wl[j][k] : Wr[j][k-256]) ----------------
__global__ void k_wcat(const float* __restrict__ Wl, const float* __restrict__ Wr,
                       float* __restrict__ wcat) {
    int idx = blockIdx.x * blockDim.x + threadIdx.x;
    if (idx < KDIM * DIM) {
        int k = idx / DIM, j = idx % DIM;
        wcat[idx] = (k < DIM) ? Wl[j * DIM + k] : Wr[j * DIM + (k - DIM)];
    }
}

// ---------------- copy root features into xcat[:,256:512] ----------------
__global__ void k_copy_root(const float* __restrict__ feat) {
    int idx = blockIdx.x * blockDim.x + threadIdx.x;     // over N*64 float4
    if (idx < N_NODES * 64) {
        int node = idx >> 6, c = idx & 63;
        reinterpret_cast<float4*>(g_xcat)[(size_t)node * 128 + 64 + c] =
            reinterpret_cast<const float4*>(feat)[idx];
    }
}

// ---------------- mean aggregation: warp per node -> xcat[:,0:256] ----------------
__global__ void k_agg(const float* __restrict__ feat) {
    int gw   = (blockIdx.x * blockDim.x + threadIdx.x) >> 5;
    int lane = threadIdx.x & 31;
    if (gw >= N_NODES) return;
    int s0 = g_rs[gw];
    int d  = g_deg[gw];
    float4 a = make_float4(0.f, 0.f, 0.f, 0.f);
    float4 b = make_float4(0.f, 0.f, 0.f, 0.f);
    for (int k = 0; k < d; k++) {
        int src = g_srt[s0 + k];
        const float4* r = reinterpret_cast<const float4*>(feat + (size_t)src * DIM);
        float4 u = __ldg(&r[lane]);
        float4 v = __ldg(&r[lane + 32]);
        a.x += u.x; a.y += u.y; a.z += u.z; a.w += u.w;
        b.x += v.x; b.y += v.y; b.z += v.z; b.w += v.w;
    }
    float sc = g_inv[gw];
    a.x *= sc; a.y *= sc; a.z *= sc; a.w *= sc;
    b.x *= sc; b.y *= sc; b.z *= sc; b.w *= sc;
    float4* o = reinterpret_cast<float4*>(g_xcat + (size_t)gw * KDIM);
    o[lane]      = a;
    o[lane + 32] = b;
}

// ---------------- fused GEMM + bias + L2-normalize (+ relu) ----------------
// C[m][j] = sum_k xcat[m][k] * wcat[k][j] + bias[j], then row-L2-normalize, optional relu.
// Block: 256 threads, BM=64 rows x full 256 cols, BK=16.
// Thread (ty=tid/32 in 0..7, tx=tid%32): rows ty*8..ty*8+7, cols tx*8..tx*8+7.
__global__ __launch_bounds__(256) void k_gemm(const float* __restrict__ wcat,
                                              const float* __restrict__ bias,
                                              float* __restrict__ out, int relu) {
    __shared__ float As[16][64];
    __shared__ float Bs[16][256];
    int tid = threadIdx.x;
    int ty = tid >> 5, tx = tid & 31;
    int m0 = blockIdx.x * 64;

    float acc[8][8];
#pragma unroll
    for (int i = 0; i < 8; i++)
#pragma unroll
        for (int j = 0; j < 8; j++) acc[i][j] = 0.f;

    int ar = tid >> 2, ac = tid & 3;     // A loader: row ar (0..63), float4 #ac within 16-k chunk
    int br = tid >> 4, bc = tid & 15;    // B loader: k-row br (0..15), 4 float4 starting bc*16

    for (int kk = 0; kk < KDIM; kk += 16) {
        float4 av = make_float4(0.f, 0.f, 0.f, 0.f);
        int row = m0 + ar;
        if (row < N_NODES)
            av = *reinterpret_cast<const float4*>(g_xcat + (size_t)row * KDIM + kk + ac * 4);
        As[ac * 4 + 0][ar] = av.x;
        As[ac * 4 + 1][ar] = av.y;
        As[ac * 4 + 2][ar] = av.z;
        As[ac * 4 + 3][ar] = av.w;
#pragma unroll
        for (int u = 0; u < 4; u++) {
            float4 bv = *reinterpret_cast<const float4*>(wcat + (size_t)(kk + br) * DIM + bc * 16 + u * 4);
            *reinterpret_cast<float4*>(&Bs[br][bc * 16 + u * 4]) = bv;
        }
        __syncthreads();
#pragma unroll
        for (int k = 0; k < 16; k++) {
            float4 a0 = *reinterpret_cast<float4*>(&As[k][ty * 8]);
            float4 a1 = *reinterpret_cast<float4*>(&As[k][ty * 8 + 4]);
            float4 b0 = *reinterpret_cast<float4*>(&Bs[k][tx * 8]);
            float4 b1 = *reinterpret_cast<float4*>(&Bs[k][tx * 8 + 4]);
            float aa[8] = {a0.x, a0.y, a0.z, a0.w, a1.x, a1.y, a1.z, a1.w};
            float bb[8] = {b0.x, b0.y, b0.z, b0.w, b1.x, b1.y, b1.z, b1.w};
#pragma unroll
            for (int i = 0; i < 8; i++)
#pragma unroll
                for (int j = 0; j < 8; j++) acc[i][j] = fmaf(aa[i], bb[j], acc[i][j]);
        }
        __syncthreads();
    }

    float bj[8];
#pragma unroll
    for (int jj = 0; jj < 8; jj++) bj[jj] = bias[tx * 8 + jj];

#pragma unroll
    for (int i = 0; i < 8; i++) {
        int row = m0 + ty * 8 + i;
        float v[8];
        float ss = 0.f;
#pragma unroll
        for (int jj = 0; jj < 8; jj++) {
            v[jj] = acc[i][jj] + bj[jj];
            ss = fmaf(v[jj], v[jj], ss);
        }
#pragma unroll
        for (int o = 16; o > 0; o >>= 1) ss += __shfl_xor_sync(0xffffffffu, ss, o);
        float nrm = sqrtf(ss);
        float sc = 1.0f / fmaxf(nrm, 1e-12f);
#pragma unroll
        for (int jj = 0; jj < 8; jj++) {
            float o = v[jj] * sc;
            if (relu) o = fmaxf(o, 0.f);
            v[jj] = o;
        }
        if (row < N_NODES) {
            float4* op = reinterpret_cast<float4*>(out + (size_t)row * DIM + tx * 8);
            op[0] = make_float4(v[0], v[1], v[2], v[3]);
            op[1] = make_float4(v[4], v[5], v[6], v[7]);
        }
    }
}

// ---------------- launch ----------------
extern "C" void kernel_launch(void* const* d_in, const int* in_sizes, int n_in,
                              void* d_out, int out_size) {
    const float* x    = (const float*)d_in[0];
    const void*  edge = d_in[1];                       // int32 or int64 — detected on device
    const float* W1l  = (const float*)d_in[2];
    const float* b1l  = (const float*)d_in[3];
    const float* W1r  = (const float*)d_in[4];
    const float* W2l  = (const float*)d_in[5];
    const float* b2l  = (const float*)d_in[6];
    const float* W2r  = (const float*)d_in[7];
    float*       out  = (float*)d_out;

    float *p_h, *p_w1, *p_w2;
    cudaGetSymbolAddress((void**)&p_h,  g_h);
    cudaGetSymbolAddress((void**)&p_w1, g_w1);
    cudaGetSymbolAddress((void**)&p_w2, g_w2);

    // edge dtype detection + CSR build (re-done every call; deterministic)
    k_detect<<<1, 32>>>((const int*)edge);
    k_zero_deg<<<(N_NODES + 255) / 256, 256>>>();
    k_hist<<<(N_EDGES + 255) / 256, 256>>>(edge);
    k_scan1<<<SCAN_NB, SCAN_B>>>();
    k_scan2<<<1, 32>>>(SCAN_NB);
    k_scan3<<<SCAN_NB, SCAN_B>>>();
    k_scatter<<<(N_EDGES + 255) / 256, 256>>>(edge);

    // weight prep
    k_wcat<<<(KDIM * DIM + 255) / 256, 256>>>(W1l, W1r, p_w1);
    k_wcat<<<(KDIM * DIM + 255) / 256, 256>>>(W2l, W2r, p_w2);

    // layer 1
    k_copy_root<<<(N_NODES * 64 + 255) / 256, 256>>>(x);
    k_agg<<<(N_NODES * 32 + 255) / 256, 256>>>(x);
    k_gemm<<<(N_NODES + 63) / 64, 256>>>(p_w1, b1l, p_h, 1);

    // layer 2
    k_copy_root<<<(N_NODES * 64 + 255) / 256, 256>>>(p_h);
    k_agg<<<(N_NODES * 32 + 255) / 256, 256>>>(p_h);
    k_gemm<<<(N_NODES + 63) / 64, 256>>>(p_w2, b2l, out, 0);
}

// round 12
// speedup vs baseline: 2.1030x; 2.1030x over previous
#include <cuda_runtime.h>
#include <cuda_bf16.h>
#include <cstdint>

#define N_NODES 50000
#define N_PAD   50176            // 392 * 128
#define N_EDGES 800000
#define DIM     256
#define KD      512              // concat(mean, root) K dimension
#define SCAN_B  1024
#define SCAN_NB 49

// ---------------- static device scratch ----------------
__device__ __nv_bfloat16 g_ahi[(size_t)N_PAD * KD];   // zero-init; pad rows never written
__device__ __nv_bfloat16 g_alo[(size_t)N_PAD * KD];
__device__ float g_h[(size_t)N_NODES * DIM];
__device__ int   g_deg[N_NODES];
__device__ float g_inv[N_NODES];
__device__ int   g_rs[N_NODES];
__device__ int   g_cur[N_NODES];
__device__ int   g_srt[N_EDGES];
__device__ int   g_bsum[64];
__device__ int   g_is64;
__device__ __nv_bfloat16 g_w1hi[DIM * KD], g_w1lo[DIM * KD];   // [n=256][k=512]
__device__ __nv_bfloat16 g_w2hi[DIM * KD], g_w2lo[DIM * KD];

// ---------------- PTX helpers (baseline ISA only — no sm_103a features) ----------------
__device__ __forceinline__ uint32_t smem_u32(const void* p) {
    uint32_t a;
    asm("{ .reg .u64 t; cvta.to.shared.u64 t, %1; cvt.u32.u64 %0, t; }" : "=r"(a) : "l"(p));
    return a;
}
__device__ __forceinline__ void cpa16(uint32_t dst, const void* src) {
    asm volatile("cp.async.cg.shared.global [%0], [%1], 16;" :: "r"(dst), "l"(src) : "memory");
}
__device__ __forceinline__ void cp_commit() {
    asm volatile("cp.async.commit_group;" ::: "memory");
}
template<int N> __device__ __forceinline__ void cp_wait() {
    asm volatile("cp.async.wait_group %0;" :: "n"(N) : "memory");
}
__device__ __forceinline__ void ldm_x4(uint32_t* r, uint32_t addr) {
    asm volatile("ldmatrix.sync.aligned.m8n8.x4.shared.b16 {%0,%1,%2,%3}, [%4];"
                 : "=r"(r[0]), "=r"(r[1]), "=r"(r[2]), "=r"(r[3]) : "r"(addr));
}
__device__ __forceinline__ void mma16816(float* c, const uint32_t* a, uint32_t b0, uint32_t b1) {
    asm volatile("mma.sync.aligned.m16n8k16.row.col.f32.bf16.bf16.f32 "
                 "{%0,%1,%2,%3}, {%4,%5,%6,%7}, {%8,%9}, {%0,%1,%2,%3};"
                 : "+f"(c[0]), "+f"(c[1]), "+f"(c[2]), "+f"(c[3])
                 : "r"(a[0]), "r"(a[1]), "r"(a[2]), "r"(a[3]), "r"(b0), "r"(b1));
}

// ---------------- edge dtype detection ----------------
__global__ void k_detect(const int* __restrict__ e32) {
    if (threadIdx.x == 0 && blockIdx.x == 0) {
        int is64 = 1;
        for (int i = 0; i < 32; i++)
            if (e32[2 * i + 1] != 0) is64 = 0;
        g_is64 = is64;
    }
}
__device__ __forceinline__ int edge_at(const void* edge, long long idx) {
    if (g_is64) return (int)((const long long*)edge)[idx];
    return ((const int*)edge)[idx];
}

// ---------------- CSR build ----------------
__global__ void k_zero_deg() {
    int i = blockIdx.x * blockDim.x + threadIdx.x;
    if (i < N_NODES) g_deg[i] = 0;
}
__global__ void k_hist(const void* __restrict__ edge) {
    int e = blockIdx.x * blockDim.x + threadIdx.x;
    if (e < N_EDGES) {
        int d = edge_at(edge, (long long)N_EDGES + e);
        if ((unsigned)d < (unsigned)N_NODES) atomicAdd(&g_deg[d], 1);
    }
}
__global__ void k_scan1() {
    __shared__ int s[SCAN_B];
    int i = blockIdx.x * SCAN_B + threadIdx.x;
    int v = (i < N_NODES) ? g_deg[i] : 0;
    s[threadIdx.x] = v;
    __syncthreads();
    for (int off = 1; off < SCAN_B; off <<= 1) {
        int t = (threadIdx.x >= off) ? s[threadIdx.x - off] : 0;
        __syncthreads();
        s[threadIdx.x] += t;
        __syncthreads();
    }
    if (i < N_NODES) g_rs[i] = s[threadIdx.x] - v;
    if (threadIdx.x == SCAN_B - 1) g_bsum[blockIdx.x] = s[SCAN_B - 1];
}
__global__ void k_scan2(int nblk) {
    if (threadIdx.x == 0 && blockIdx.x == 0) {
        int acc = 0;
        for (int b = 0; b < nblk; b++) { int t = g_bsum[b]; g_bsum[b] = acc; acc += t; }
    }
}
__global__ void k_scan3() {
    int i = blockIdx.x * SCAN_B + threadIdx.x;
    if (i < N_NODES) {
        int rs = g_rs[i] + g_bsum[blockIdx.x];
        g_rs[i]  = rs;
        g_cur[i] = rs;
        int d = g_deg[i];
        g_inv[i] = 1.0f / (float)(d > 1 ? d : 1);
    }
}
__global__ void k_scatter(const void* __restrict__ edge) {
    int e = blockIdx.x * blockDim.x + threadIdx.x;
    if (e < N_EDGES) {
        int d = edge_at(edge, (long long)N_EDGES + e);
        if ((unsigned)d < (unsigned)N_NODES) {
            int s = edge_at(edge, e);
            if ((unsigned)s >= (unsigned)N_NODES) s = 0;
            int p = atomicAdd(&g_cur[d], 1);
            g_srt[p] = s;
        }
    }
}

// ---------------- weight split: B[n][k] = (k<256 ? Wl[n][k] : Wr[n][k-256]) as bf16 hi+lo ----------------
__global__ void k_wsplit(const float* __restrict__ Wl, const float* __restrict__ Wr,
                         __nv_bfloat16* __restrict__ whi, __nv_bfloat16* __restrict__ wlo) {
    int idx = blockIdx.x * blockDim.x + threadIdx.x;
    if (idx < DIM * KD) {
        int n = idx >> 9, k = idx & 511;
        float v = (k < DIM) ? Wl[n * DIM + k] : Wr[n * DIM + (k - DIM)];
        __nv_bfloat16 h = __float2bfloat16(v);
        whi[idx] = h;
        wlo[idx] = __float2bfloat16(v - __bfloat162float(h));
    }
}

// ---------------- split-store helper: 4 floats -> bf16 hi/lo ----------------
__device__ __forceinline__ void st_split4(__nv_bfloat16* hp, __nv_bfloat16* lp, float4 v) {
    __nv_bfloat16 h0 = __float2bfloat16(v.x), h1 = __float2bfloat16(v.y);
    __nv_bfloat16 h2 = __float2bfloat16(v.z), h3 = __float2bfloat16(v.w);
    __nv_bfloat162 a, b;
    a.x = h0; a.y = h1; b.x = h2; b.y = h3;
    ((__nv_bfloat162*)hp)[0] = a; ((__nv_bfloat162*)hp)[1] = b;
    a.x = __float2bfloat16(v.x - __bfloat162float(h0));
    a.y = __float2bfloat16(v.y - __bfloat162float(h1));
    b.x = __float2bfloat16(v.z - __bfloat162float(h2));
    b.y = __float2bfloat16(v.w - __bfloat162float(h3));
    ((__nv_bfloat162*)lp)[0] = a; ((__nv_bfloat162*)lp)[1] = b;
}

// ---------------- fused mean-agg + root-copy, output bf16 hi/lo [N_PAD x 512] ----------------
__global__ void k_aggsplit(const float* __restrict__ feat) {
    int gw   = (blockIdx.x * blockDim.x + threadIdx.x) >> 5;
    int lane = threadIdx.x & 31;
    if (gw >= N_NODES) return;
    int s0 = g_rs[gw];
    int d  = g_deg[gw];
    float4 a = make_float4(0.f, 0.f, 0.f, 0.f);
    float4 b = make_float4(0.f, 0.f, 0.f, 0.f);
    for (int k = 0; k < d; k++) {
        int src = g_srt[s0 + k];
        const float4* r = reinterpret_cast<const float4*>(feat + (size_t)src * DIM);
        float4 u = __ldg(&r[lane]);
        float4 v = __ldg(&r[lane + 32]);
        a.x += u.x; a.y += u.y; a.z += u.z; a.w += u.w;
        b.x += v.x; b.y += v.y; b.z += v.z; b.w += v.w;
    }
    float sc = g_inv[gw];
    a.x *= sc; a.y *= sc; a.z *= sc; a.w *= sc;
    b.x *= sc; b.y *= sc; b.z *= sc; b.w *= sc;
    const float4* rr = reinterpret_cast<const float4*>(feat + (size_t)gw * DIM);
    float4 c0 = __ldg(&rr[lane]);
    float4 c1 = __ldg(&rr[lane + 32]);
    __nv_bfloat16* hb = g_ahi + (size_t)gw * KD;
    __nv_bfloat16* lb = g_alo + (size_t)gw * KD;
    st_split4(hb + 4 * lane,       lb + 4 * lane,       a);
    st_split4(hb + 128 + 4 * lane, lb + 128 + 4 * lane, b);
    st_split4(hb + 256 + 4 * lane, lb + 256 + 4 * lane, c0);
    st_split4(hb + 384 + 4 * lane, lb + 384 + 4 * lane, c1);
}

// ---------------- HMMA GEMM: C[128m x 256n] = A[128x512] @ W^T, 3xBF16, fused bias+L2norm(+relu) ----------------
// SMEM (bytes): two stages of {Ahi[128][40], Alo, Whi[256][40], Wlo} halves (pad 32->40 for ldmatrix),
// then bias[256]f, ss[128]f.
#define RS        40                       // row stride in halves (80 B)
#define AHI_OFF   0
#define ALO_OFF   10240
#define WHI_OFF   20480
#define WLO_OFF   40960
#define STAGE_SZ  61440
#define BIAS_OFF  122880
#define SS_OFF    123904
#define SM_TOTAL  124928

__device__ __forceinline__ void load_stage(uint32_t sb, int stage, int m0, int k0,
                                           const __nv_bfloat16* whi, const __nv_bfloat16* wlo,
                                           int tid) {
    uint32_t base = sb + stage * STAGE_SZ;
#pragma unroll
    for (int u = 0; u < 2; u++) {                       // A hi/lo: 512 chunks each
        int c = u * 256 + tid;
        int row = c >> 2, seg = c & 3;
        size_t gofs = (size_t)(m0 + row) * KD + k0 + seg * 8;
        cpa16(base + AHI_OFF + row * 80 + seg * 16, g_ahi + gofs);
        cpa16(base + ALO_OFF + row * 80 + seg * 16, g_alo + gofs);
    }
#pragma unroll
    for (int u = 0; u < 4; u++) {                       // W hi/lo: 1024 chunks each
        int c = u * 256 + tid;
        int row = c >> 2, seg = c & 3;
        size_t gofs = (size_t)row * KD + k0 + seg * 8;
        cpa16(base + WHI_OFF + row * 80 + seg * 16, whi + gofs);
        cpa16(base + WLO_OFF + row * 80 + seg * 16, wlo + gofs);
    }
    cp_commit();
}

__global__ __launch_bounds__(256, 1) void k_gemm_mma(
    const __nv_bfloat16* __restrict__ whi, const __nv_bfloat16* __restrict__ wlo,
    const float* __restrict__ bias, float* __restrict__ out, int relu) {
    extern __shared__ char smem[];
    uint32_t sb = smem_u32(smem);
    int tid = threadIdx.x, wid = tid >> 5, lane = tid & 31;
    int wr = wid >> 2, wc = wid & 3;                    // warp grid 2 x 4, warp tile 64 x 64
    int m0 = blockIdx.x * 128;

    ((float*)(smem + BIAS_OFF))[tid] = bias[tid];       // tid < 256

    float acc[4][8][4];
#pragma unroll
    for (int i = 0; i < 4; i++)
#pragma unroll
        for (int j = 0; j < 8; j++)
#pragma unroll
            for (int q = 0; q < 4; q++) acc[i][j][q] = 0.f;

    load_stage(sb, 0, m0, 0, whi, wlo, tid);

    int moff = lane & 15;                               // ldmatrix row-within-tile
    int kseg = (lane >> 4) * 8;                         // halves

    for (int s = 0; s < 16; s++) {                      // 16 stages of BK=32
        if (s + 1 < 16) load_stage(sb, (s + 1) & 1, m0, (s + 1) * 32, whi, wlo, tid);
        if (s + 1 < 16) cp_wait<1>(); else cp_wait<0>();
        __syncthreads();

        uint32_t stg = sb + (s & 1) * STAGE_SZ;
#pragma unroll
        for (int t = 0; t < 2; t++) {                   // two k16 per stage
            uint32_t ah[4][4], al[4][4], bh[4][4], bl[4][4];
#pragma unroll
            for (int i = 0; i < 4; i++) {
                uint32_t ao = (uint32_t)((wr * 64 + i * 16 + moff) * RS + t * 16 + kseg) * 2;
                ldm_x4(ah[i], stg + AHI_OFF + ao);
                ldm_x4(al[i], stg + ALO_OFF + ao);
            }
#pragma unroll
            for (int p = 0; p < 4; p++) {
                uint32_t bo = (uint32_t)((wc * 64 + p * 16 + moff) * RS + t * 16 + kseg) * 2;
                ldm_x4(bh[p], stg + WHI_OFF + bo);
                ldm_x4(bl[p], stg + WLO_OFF + bo);
            }
#pragma unroll
            for (int i = 0; i < 4; i++)
#pragma unroll
                for (int j = 0; j < 8; j++) {
                    int p = j >> 1, q = j & 1;
                    mma16816(acc[i][j], ah[i], bh[p][q], bh[p][q + 2]);   // hi*hi
                    mma16816(acc[i][j], ah[i], bl[p][q], bl[p][q + 2]);   // hi*lo
                    mma16816(acc[i][j], al[i], bh[p][q], bh[p][q + 2]);   // lo*hi
                }
        }
        __syncthreads();
    }

    // ---------------- epilogue: bias + row L2 norm + (relu) + store ----------------
    float* ssm = (float*)(smem + SS_OFF);
    const float* bsm = (const float*)(smem + BIAS_OFF);
    if (tid < 128) ssm[tid] = 0.f;
    __syncthreads();

    int qr = lane >> 2, qc = lane & 3;
#pragma unroll
    for (int i = 0; i < 4; i++) {
        int r0 = wr * 64 + i * 16 + qr;                 // and r0+8
        float s0 = 0.f, s1 = 0.f;
#pragma unroll
        for (int j = 0; j < 8; j++) {
            int col = wc * 64 + j * 8 + qc * 2;
            float b0 = bsm[col], b1 = bsm[col + 1];
            acc[i][j][0] += b0; acc[i][j][1] += b1;
            acc[i][j][2] += b0; acc[i][j][3] += b1;
            s0 = fmaf(acc[i][j][0], acc[i][j][0], s0);
            s0 = fmaf(acc[i][j][1], acc[i][j][1], s0);
            s1 = fmaf(acc[i][j][2], acc[i][j][2], s1);
            s1 = fmaf(acc[i][j][3], acc[i][j][3], s1);
        }
        s0 += __shfl_xor_sync(0xffffffffu, s0, 1);
        s0 += __shfl_xor_sync(0xffffffffu, s0, 2);
        s1 += __shfl_xor_sync(0xffffffffu, s1, 1);
        s1 += __shfl_xor_sync(0xffffffffu, s1, 2);
        if (qc == 0) {
            atomicAdd(&ssm[r0], s0);
            atomicAdd(&ssm[r0 + 8], s1);
        }
    }
    __syncthreads();

#pragma unroll
    for (int i = 0; i < 4; i++) {
        int r0 = wr * 64 + i * 16 + qr;
        float sc0 = 1.0f / fmaxf(sqrtf(ssm[r0]),     1e-12f);
        float sc1 = 1.0f / fmaxf(sqrtf(ssm[r0 + 8]), 1e-12f);
        int g0 = m0 + r0, g1 = g0 + 8;
#pragma unroll
        for (int j = 0; j < 8; j++) {
            int col = wc * 64 + j * 8 + qc * 2;
            float2 v0, v1;
            v0.x = acc[i][j][0] * sc0; v0.y = acc[i][j][1] * sc0;
            v1.x = acc[i][j][2] * sc1; v1.y = acc[i][j][3] * sc1;
            if (relu) {
                v0.x = fmaxf(v0.x, 0.f); v0.y = fmaxf(v0.y, 0.f);
                v1.x = fmaxf(v1.x, 0.f); v1.y = fmaxf(v1.y, 0.f);
            }
            if (g0 < N_NODES) *reinterpret_cast<float2*>(out + (size_t)g0 * DIM + col) = v0;
            if (g1 < N_NODES) *reinterpret_cast<float2*>(out + (size_t)g1 * DIM + col) = v1;
        }
    }
}

// ---------------- launch ----------------
extern "C" void kernel_launch(void* const* d_in, const int* in_sizes, int n_in,
                              void* d_out, int out_size) {
    const float* x    = (const float*)d_in[0];
    const void*  edge = d_in[1];
    const float* W1l  = (const float*)d_in[2];
    const float* b1l  = (const float*)d_in[3];
    const float* W1r  = (const float*)d_in[4];
    const float* W2l  = (const float*)d_in[5];
    const float* b2l  = (const float*)d_in[6];
    const float* W2r  = (const float*)d_in[7];
    float*       out  = (float*)d_out;

    float* p_h;
    __nv_bfloat16 *p_w1h, *p_w1l, *p_w2h, *p_w2l;
    cudaGetSymbolAddress((void**)&p_h,   g_h);
    cudaGetSymbolAddress((void**)&p_w1h, g_w1hi);
    cudaGetSymbolAddress((void**)&p_w1l, g_w1lo);
    cudaGetSymbolAddress((void**)&p_w2h, g_w2hi);
    cudaGetSymbolAddress((void**)&p_w2l, g_w2lo);

    cudaFuncSetAttribute(k_gemm_mma, cudaFuncAttributeMaxDynamicSharedMemorySize, SM_TOTAL);

    // edge dtype + CSR build
    k_detect<<<1, 32>>>((const int*)edge);
    k_zero_deg<<<(N_NODES + 255) / 256, 256>>>();
    k_hist<<<(N_EDGES + 255) / 256, 256>>>(edge);
    k_scan1<<<SCAN_NB, SCAN_B>>>();
    k_scan2<<<1, 32>>>(SCAN_NB);
    k_scan3<<<SCAN_NB, SCAN_B>>>();
    k_scatter<<<(N_EDGES + 255) / 256, 256>>>(edge);

    // weight split
    k_wsplit<<<(DIM * KD + 255) / 256, 256>>>(W1l, W1r, p_w1h, p_w1l);
    k_wsplit<<<(DIM * KD + 255) / 256, 256>>>(W2l, W2r, p_w2h, p_w2l);

    // layer 1
    k_aggsplit<<<(N_NODES * 32 + 255) / 256, 256>>>(x);
    k_gemm_mma<<<N_PAD / 128, 256, SM_TOTAL>>>(p_w1h, p_w1l, b1l, p_h, 1);

    // layer 2
    k_aggsplit<<<(N_NODES * 32 + 255) / 256, 256>>>(p_h);
    k_gemm_mma<<<N_PAD / 128, 256, SM_TOTAL>>>(p_w2h, p_w2l, b2l, out, 0);
}

// round 15
// speedup vs baseline: 2.1171x; 1.0067x over previous
#include <cuda_runtime.h>
#include <cuda_bf16.h>
#include <cstdint>

#define N_NODES 50000
#define N_PAD   50176            // 392 * 128
#define N_EDGES 800000
#define DIM     256
#define KD      512              // concat(mean, root) K dimension
#define SCAN_B  1024
#define SCAN_NB 49

// ---------------- static device scratch ----------------
__device__ __nv_bfloat16 g_ahi[(size_t)N_PAD * KD];   // zero-init; pad rows never written
__device__ __nv_bfloat16 g_alo[(size_t)N_PAD * KD];
__device__ float g_h[(size_t)N_NODES * DIM];
__device__ int   g_deg[N_NODES];
__device__ float g_inv[N_NODES];
__device__ int   g_rs[N_NODES];
__device__ int   g_cur[N_NODES];
__device__ int   g_srt[N_EDGES];
__device__ int   g_bsum[64];
__device__ int   g_is64;
__device__ __nv_bfloat16 g_w1hi[DIM * KD], g_w1lo[DIM * KD];   // [n=256][k=512]
__device__ __nv_bfloat16 g_w2hi[DIM * KD], g_w2lo[DIM * KD];

// ---------------- PTX helpers (baseline ISA only — no sm_103a features) ----------------
__device__ __forceinline__ uint32_t smem_u32(const void* p) {
    uint32_t a;
    asm("{ .reg .u64 t; cvta.to.shared.u64 t, %1; cvt.u32.u64 %0, t; }" : "=r"(a) : "l"(p));
    return a;
}
__device__ __forceinline__ void cpa16(uint32_t dst, const void* src) {
    asm volatile("cp.async.cg.shared.global [%0], [%1], 16;" :: "r"(dst), "l"(src) : "memory");
}
__device__ __forceinline__ void cp_commit() {
    asm volatile("cp.async.commit_group;" ::: "memory");
}
template<int N> __device__ __forceinline__ void cp_wait() {
    asm volatile("cp.async.wait_group %0;" :: "n"(N) : "memory");
}
__device__ __forceinline__ void ldm_x4(uint32_t* r, uint32_t addr) {
    asm volatile("ldmatrix.sync.aligned.m8n8.x4.shared.b16 {%0,%1,%2,%3}, [%4];"
                 : "=r"(r[0]), "=r"(r[1]), "=r"(r[2]), "=r"(r[3]) : "r"(addr));
}
__device__ __forceinline__ void mma16816(float* c, const uint32_t* a, uint32_t b0, uint32_t b1) {
    asm volatile("mma.sync.aligned.m16n8k16.row.col.f32.bf16.bf16.f32 "
                 "{%0,%1,%2,%3}, {%4,%5,%6,%7}, {%8,%9}, {%0,%1,%2,%3};"
                 : "+f"(c[0]), "+f"(c[1]), "+f"(c[2]), "+f"(c[3])
                 : "r"(a[0]), "r"(a[1]), "r"(a[2]), "r"(a[3]), "r"(b0), "r"(b1));
}

// ---------------- CSR build (detect folded into zero kernel) ----------------
__global__ void k_zero_detect(const int* __restrict__ e32) {
    int i = blockIdx.x * blockDim.x + threadIdx.x;
    if (i < N_NODES) g_deg[i] = 0;
    if (i == 0) {
        // int64 vs int32 layout detection: for LE int64 node ids < 50000,
        // every odd 32-bit word is 0; genuine int32 data never has 32 zeros.
        int is64 = 1;
        for (int t = 0; t < 32; t++)
            if (e32[2 * t + 1] != 0) is64 = 0;
        g_is64 = is64;
    }
}
__device__ __forceinline__ int edge_at(const void* edge, long long idx) {
    if (g_is64) return (int)((const long long*)edge)[idx];
    return ((const int*)edge)[idx];
}
__global__ void k_hist(const void* __restrict__ edge) {
    int e = blockIdx.x * blockDim.x + threadIdx.x;
    if (e < N_EDGES) {
        int d = edge_at(edge, (long long)N_EDGES + e);
        if ((unsigned)d < (unsigned)N_NODES) atomicAdd(&g_deg[d], 1);
    }
}
__global__ void k_scan1() {
    __shared__ int s[SCAN_B];
    int i = blockIdx.x * SCAN_B + threadIdx.x;
    int v = (i < N_NODES) ? g_deg[i] : 0;
    s[threadIdx.x] = v;
    __syncthreads();
    for (int off = 1; off < SCAN_B; off <<= 1) {
        int t = (threadIdx.x >= off) ? s[threadIdx.x - off] : 0;
        __syncthreads();
        s[threadIdx.x] += t;
        __syncthreads();
    }
    if (i < N_NODES) g_rs[i] = s[threadIdx.x] - v;
    if (threadIdx.x == SCAN_B - 1) g_bsum[blockIdx.x] = s[SCAN_B - 1];
}
__global__ void k_scan2(int nblk) {
    if (threadIdx.x == 0 && blockIdx.x == 0) {
        int acc = 0;
        for (int b = 0; b < nblk; b++) { int t = g_bsum[b]; g_bsum[b] = acc; acc += t; }
    }
}
__global__ void k_scan3() {
    int i = blockIdx.x * SCAN_B + threadIdx.x;
    if (i < N_NODES) {
        int rs = g_rs[i] + g_bsum[blockIdx.x];
        g_rs[i]  = rs;
        g_cur[i] = rs;
        int d = g_deg[i];
        g_inv[i] = 1.0f / (float)(d > 1 ? d : 1);
    }
}
__global__ void k_scatter(const void* __restrict__ edge) {
    int e = blockIdx.x * blockDim.x + threadIdx.x;
    if (e < N_EDGES) {
        int d = edge_at(edge, (long long)N_EDGES + e);
        if ((unsigned)d < (unsigned)N_NODES) {
            int s = edge_at(edge, e);
            if ((unsigned)s >= (unsigned)N_NODES) s = 0;
            int p = atomicAdd(&g_cur[d], 1);
            g_srt[p] = s;
        }
    }
}

// ---------------- weight split: B[n][k] = (k<256 ? Wl[n][k] : Wr[n][k-256]) as bf16 hi+lo ----------------
__global__ void k_wsplit(const float* __restrict__ Wl, const float* __restrict__ Wr,
                         __nv_bfloat16* __restrict__ whi, __nv_bfloat16* __restrict__ wlo) {
    int idx = blockIdx.x * blockDim.x + threadIdx.x;
    if (idx < DIM * KD) {
        int n = idx >> 9, k = idx & 511;
        float v = (k < DIM) ? Wl[n * DIM + k] : Wr[n * DIM + (k - DIM)];
        __nv_bfloat16 h = __float2bfloat16(v);
        whi[idx] = h;
        wlo[idx] = __float2bfloat16(v - __bfloat162float(h));
    }
}

// ---------------- split-store helper: 4 floats -> bf16 hi/lo ----------------
__device__ __forceinline__ void st_split4(__nv_bfloat16* hp, __nv_bfloat16* lp, float4 v) {
    __nv_bfloat16 h0 = __float2bfloat16(v.x), h1 = __float2bfloat16(v.y);
    __nv_bfloat16 h2 = __float2bfloat16(v.z), h3 = __float2bfloat16(v.w);
    __nv_bfloat162 a, b;
    a.x = h0; a.y = h1; b.x = h2; b.y = h3;
    ((__nv_bfloat162*)hp)[0] = a; ((__nv_bfloat162*)hp)[1] = b;
    a.x = __float2bfloat16(v.x - __bfloat162float(h0));
    a.y = __float2bfloat16(v.y - __bfloat162float(h1));
    b.x = __float2bfloat16(v.z - __bfloat162float(h2));
    b.y = __float2bfloat16(v.w - __bfloat162float(h3));
    ((__nv_bfloat162*)lp)[0] = a; ((__nv_bfloat162*)lp)[1] = b;
}
__device__ __forceinline__ void acc4(float4& a, float4 u) {
    a.x += u.x; a.y += u.y; a.z += u.z; a.w += u.w;
}

// ---------------- fused mean-agg + root-copy, output bf16 hi/lo [N_PAD x 512] ----------------
// Edge loop unrolled x4 with indices prefetched -> 8 independent float4 gathers
// in flight per warp (MLP 8) instead of 2, to cover L2 latency.
__global__ void k_aggsplit(const float* __restrict__ feat) {
    int gw   = (blockIdx.x * blockDim.x + threadIdx.x) >> 5;
    int lane = threadIdx.x & 31;
    if (gw >= N_NODES) return;
    int s0 = g_rs[gw];
    int d  = g_deg[gw];
    float4 a = make_float4(0.f, 0.f, 0.f, 0.f);
    float4 b = make_float4(0.f, 0.f, 0.f, 0.f);
    int k = 0;
    int dm4 = d & ~3;
    for (; k < dm4; k += 4) {
        int i0 = g_srt[s0 + k + 0];
        int i1 = g_srt[s0 + k + 1];
        int i2 = g_srt[s0 + k + 2];
        int i3 = g_srt[s0 + k + 3];
        const float4* r0 = reinterpret_cast<const float4*>(feat + (size_t)i0 * DIM);
        const float4* r1 = reinterpret_cast<const float4*>(feat + (size_t)i1 * DIM);
        const float4* r2 = reinterpret_cast<const float4*>(feat + (size_t)i2 * DIM);
        const float4* r3 = reinterpret_cast<const float4*>(feat + (size_t)i3 * DIM);
        float4 u0 = __ldg(&r0[lane]),      u1 = __ldg(&r1[lane]);
        float4 u2 = __ldg(&r2[lane]),      u3 = __ldg(&r3[lane]);
        float4 v0 = __ldg(&r0[lane + 32]), v1 = __ldg(&r1[lane + 32]);
        float4 v2 = __ldg(&r2[lane + 32]), v3 = __ldg(&r3[lane + 32]);
        acc4(a, u0); acc4(a, u1); acc4(a, u2); acc4(a, u3);
        acc4(b, v0); acc4(b, v1); acc4(b, v2); acc4(b, v3);
    }
    for (; k < d; k++) {
        int src = g_srt[s0 + k];
        const float4* r = reinterpret_cast<const float4*>(feat + (size_t)src * DIM);
        acc4(a, __ldg(&r[lane]));
        acc4(b, __ldg(&r[lane + 32]));
    }
    float sc = g_inv[gw];
    a.x *= sc; a.y *= sc; a.z *= sc; a.w *= sc;
    b.x *= sc; b.y *= sc; b.z *= sc; b.w *= sc;
    const float4* rr = reinterpret_cast<const float4*>(feat + (size_t)gw * DIM);
    float4 c0 = __ldg(&rr[lane]);
    float4 c1 = __ldg(&rr[lane + 32]);
    __nv_bfloat16* hb = g_ahi + (size_t)gw * KD;
    __nv_bfloat16* lb = g_alo + (size_t)gw * KD;
    st_split4(hb + 4 * lane,       lb + 4 * lane,       a);
    st_split4(hb + 128 + 4 * lane, lb + 128 + 4 * lane, b);
    st_split4(hb + 256 + 4 * lane, lb + 256 + 4 * lane, c0);
    st_split4(hb + 384 + 4 * lane, lb + 384 + 4 * lane, c1);
}

// ---------------- HMMA GEMM: C[128m x 256n] = A[128x512] @ W^T, 3xBF16, fused bias+L2norm(+relu) ----------------
#define RS        40                       // row stride in halves (80 B)
#define AHI_OFF   0
#define ALO_OFF   10240
#define WHI_OFF   20480
#define WLO_OFF   40960
#define STAGE_SZ  61440
#define BIAS_OFF  122880
#define SS_OFF    123904
#define SM_TOTAL  124928

__device__ __forceinline__ void load_stage(uint32_t sb, int stage, int m0, int k0,
                                           const __nv_bfloat16* whi, const __nv_bfloat16* wlo,
                                           int tid) {
    uint32_t base = sb + stage * STAGE_SZ;
#pragma unroll
    for (int u = 0; u < 2; u++) {                       // A hi/lo: 512 chunks each
        int c = u * 256 + tid;
        int row = c >> 2, seg = c & 3;
        size_t gofs = (size_t)(m0 + row) * KD + k0 + seg * 8;
        cpa16(base + AHI_OFF + row * 80 + seg * 16, g_ahi + gofs);
        cpa16(base + ALO_OFF + row * 80 + seg * 16, g_alo + gofs);
    }
#pragma unroll
    for (int u = 0; u < 4; u++) {                       // W hi/lo: 1024 chunks each
        int c = u * 256 + tid;
        int row = c >> 2, seg = c & 3;
        size_t gofs = (size_t)row * KD + k0 + seg * 8;
        cpa16(base + WHI_OFF + row * 80 + seg * 16, whi + gofs);
        cpa16(base + WLO_OFF + row * 80 + seg * 16, wlo + gofs);
    }
    cp_commit();
}

__global__ __launch_bounds__(256, 1) void k_gemm_mma(
    const __nv_bfloat16* __restrict__ whi, const __nv_bfloat16* __restrict__ wlo,
    const float* __restrict__ bias, float* __restrict__ out, int relu) {
    extern __shared__ char smem[];
    uint32_t sb = smem_u32(smem);
    int tid = threadIdx.x, wid = tid >> 5, lane = tid & 31;
    int wr = wid >> 2, wc = wid & 3;                    // warp grid 2 x 4, warp tile 64 x 64
    int m0 = blockIdx.x * 128;

    ((float*)(smem + BIAS_OFF))[tid] = bias[tid];       // tid < 256

    float acc[4][8][4];
#pragma unroll
    for (int i = 0; i < 4; i++)
#pragma unroll
        for (int j = 0; j < 8; j++)
#pragma unroll
            for (int q = 0; q < 4; q++) acc[i][j][q] = 0.f;

    load_stage(sb, 0, m0, 0, whi, wlo, tid);

    int moff = lane & 15;                               // ldmatrix row-within-tile
    int kseg = (lane >> 4) * 8;                         // halves

    for (int s = 0; s < 16; s++) {                      // 16 stages of BK=32
        if (s + 1 < 16) load_stage(sb, (s + 1) & 1, m0, (s + 1) * 32, whi, wlo, tid);
        if (s + 1 < 16) cp_wait<1>(); else cp_wait<0>();
        __syncthreads();

        uint32_t stg = sb + (s & 1) * STAGE_SZ;
#pragma unroll
        for (int t = 0; t < 2; t++) {                   // two k16 per stage
            uint32_t ah[4][4], al[4][4], bh[4][4], bl[4][4];
#pragma unroll
            for (int i = 0; i < 4; i++) {
                uint32_t ao = (uint32_t)((wr * 64 + i * 16 + moff) * RS + t * 16 + kseg) * 2;
                ldm_x4(ah[i], stg + AHI_OFF + ao);
                ldm_x4(al[i], stg + ALO_OFF + ao);
            }
#pragma unroll
            for (int p = 0; p < 4; p++) {
                uint32_t bo = (uint32_t)((wc * 64 + p * 16 + moff) * RS + t * 16 + kseg) * 2;
                ldm_x4(bh[p], stg + WHI_OFF + bo);
                ldm_x4(bl[p], stg + WLO_OFF + bo);
            }
#pragma unroll
            for (int i = 0; i < 4; i++)
#pragma unroll
                for (int j = 0; j < 8; j++) {
                    int p = j >> 1, q = j & 1;
                    mma16816(acc[i][j], ah[i], bh[p][q], bh[p][q + 2]);   // hi*hi
                    mma16816(acc[i][j], ah[i], bl[p][q], bl[p][q + 2]);   // hi*lo
                    mma16816(acc[i][j], al[i], bh[p][q], bh[p][q + 2]);   // lo*hi
                }
        }
        __syncthreads();
    }

    // ---------------- epilogue: bias + row L2 norm + (relu) + store ----------------
    float* ssm = (float*)(smem + SS_OFF);
    const float* bsm = (const float*)(smem + BIAS_OFF);
    if (tid < 128) ssm[tid] = 0.f;
    __syncthreads();

    int qr = lane >> 2, qc = lane & 3;
#pragma unroll
    for (int i = 0; i < 4; i++) {
        int r0 = wr * 64 + i * 16 + qr;                 // and r0+8
        float s0 = 0.f, s1 = 0.f;
#pragma unroll
        for (int j = 0; j < 8; j++) {
            int col = wc * 64 + j * 8 + qc * 2;
            float b0 = bsm[col], b1 = bsm[col + 1];
            acc[i][j][0] += b0; acc[i][j][1] += b1;
            acc[i][j][2] += b0; acc[i][j][3] += b1;
            s0 = fmaf(acc[i][j][0], acc[i][j][0], s0);
            s0 = fmaf(acc[i][j][1], acc[i][j][1], s0);
            s1 = fmaf(acc[i][j][2], acc[i][j][2], s1);
            s1 = fmaf(acc[i][j][3], acc[i][j][3], s1);
        }
        s0 += __shfl_xor_sync(0xffffffffu, s0, 1);
        s0 += __shfl_xor_sync(0xffffffffu, s0, 2);
        s1 += __shfl_xor_sync(0xffffffffu, s1, 1);
        s1 += __shfl_xor_sync(0xffffffffu, s1, 2);
        if (qc == 0) {
            atomicAdd(&ssm[r0], s0);
            atomicAdd(&ssm[r0 + 8], s1);
        }
    }
    __syncthreads();

#pragma unroll
    for (int i = 0; i < 4; i++) {
        int r0 = wr * 64 + i * 16 + qr;
        float sc0 = 1.0f / fmaxf(sqrtf(ssm[r0]),     1e-12f);
        float sc1 = 1.0f / fmaxf(sqrtf(ssm[r0 + 8]), 1e-12f);
        int g0 = m0 + r0, g1 = g0 + 8;
#pragma unroll
        for (int j = 0; j < 8; j++) {
            int col = wc * 64 + j * 8 + qc * 2;
            float2 v0, v1;
            v0.x = acc[i][j][0] * sc0; v0.y = acc[i][j][1] * sc0;
            v1.x = acc[i][j][2] * sc1; v1.y = acc[i][j][3] * sc1;
            if (relu) {
                v0.x = fmaxf(v0.x, 0.f); v0.y = fmaxf(v0.y, 0.f);
                v1.x = fmaxf(v1.x, 0.f); v1.y = fmaxf(v1.y, 0.f);
            }
            if (g0 < N_NODES) *reinterpret_cast<float2*>(out + (size_t)g0 * DIM + col) = v0;
            if (g1 < N_NODES) *reinterpret_cast<float2*>(out + (size_t)g1 * DIM + col) = v1;
        }
    }
}

// ---------------- launch ----------------
extern "C" void kernel_launch(void* const* d_in, const int* in_sizes, int n_in,
                              void* d_out, int out_size) {
    const float* x    = (const float*)d_in[0];
    const void*  edge = d_in[1];
    const float* W1l  = (const float*)d_in[2];
    const float* b1l  = (const float*)d_in[3];
    const float* W1r  = (const float*)d_in[4];
    const float* W2l  = (const float*)d_in[5];
    const float* b2l  = (const float*)d_in[6];
    const float* W2r  = (const float*)d_in[7];
    float*       out  = (float*)d_out;

    float* p_h;
    __nv_bfloat16 *p_w1h, *p_w1l, *p_w2h, *p_w2l;
    cudaGetSymbolAddress((void**)&p_h,   g_h);
    cudaGetSymbolAddress((void**)&p_w1h, g_w1hi);
    cudaGetSymbolAddress((void**)&p_w1l, g_w1lo);
    cudaGetSymbolAddress((void**)&p_w2h, g_w2hi);
    cudaGetSymbolAddress((void**)&p_w2l, g_w2lo);

    cudaFuncSetAttribute(k_gemm_mma, cudaFuncAttributeMaxDynamicSharedMemorySize, SM_TOTAL);

    // CSR build (detect fused into zero kernel)
    k_zero_detect<<<(N_NODES + 255) / 256, 256>>>((const int*)edge);
    k_hist<<<(N_EDGES + 255) / 256, 256>>>(edge);
    k_scan1<<<SCAN_NB, SCAN_B>>>();
    k_scan2<<<1, 32>>>(SCAN_NB);
    k_scan3<<<SCAN_NB, SCAN_B>>>();
    k_scatter<<<(N_EDGES + 255) / 256, 256>>>(edge);

    // weight split
    k_wsplit<<<(DIM * KD + 255) / 256, 256>>>(W1l, W1r, p_w1h, p_w1l);
    k_wsplit<<<(DIM * KD + 255) / 256, 256>>>(W2l, W2r, p_w2h, p_w2l);

    // layer 1
    k_aggsplit<<<(N_NODES * 32 + 255) / 256, 256>>>(x);
    k_gemm_mma<<<N_PAD / 128, 256, SM_TOTAL>>>(p_w1h, p_w1l, b1l, p_h, 1);

    // layer 2
    k_aggsplit<<<(N_NODES * 32 + 255) / 256, 256>>>(p_h);
    k_gemm_mma<<<N_PAD / 128, 256, SM_TOTAL>>>(p_w2h, p_w2l, b2l, out, 0);
}